// round 6
// baseline (speedup 1.0000x reference)
#include <cuda_runtime.h>

// ChamferLossSplit: B=256, N=M=256, D=4, PID_MAX=5.
// Inputs: target f32 [B,N,4], reco f32 [B,M,4], in_pid i32 [B,N], out_pid i32 [B,M]
// Output: f32[2] = (mean per_nonzero, mean per_zero)
//
// Shuffle-ring + packed f32x2 math: each lane holds 8 target rows (lane+32k),
// pre-packed in row pairs for fma.rn.f32x2. Each warp owns 32 recos; one reco
// per lane circulates via shfl carrying its column-min. After 32 rotations the
// complete column min lands back on its home lane. Row mins are per-warp
// partials combined once via smem slabs.

#define NPTS 256
#define NWARP 8
#define RPL 8          // rows per lane
#define BIGC 1e18f     // sentinel coord for invalid points (4*BIGC^2 finite)
#define FULLMASK 0xffffffffu

typedef unsigned long long ull;

#define FMA2(d, a, b, c) asm("fma.rn.f32x2 %0, %1, %2, %3;" : "=l"(d) : "l"(a), "l"(b), "l"(c))
#define MUL2(d, a, b)    asm("mul.rn.f32x2 %0, %1, %2;"     : "=l"(d) : "l"(a), "l"(b))
#define ADD2(d, a, b)    asm("add.rn.f32x2 %0, %1, %2;"     : "=l"(d) : "l"(a), "l"(b))
#define PACK2(d, lo, hi) asm("mov.b64 %0, {%1, %2};"        : "=l"(d) : "f"(lo), "f"(hi))
#define UNPK2(lo, hi, v) asm("mov.b64 {%0, %1}, %2;"        : "=f"(lo), "=f"(hi) : "l"(v))

__device__ __forceinline__ float warp_sum(float v) {
    #pragma unroll
    for (int o = 16; o; o >>= 1) v += __shfl_xor_sync(FULLMASK, v, o);
    return v;
}

__global__ __launch_bounds__(NPTS) void chamfer_kernel(
    const float4* __restrict__ target,
    const float4* __restrict__ reco,
    const int* __restrict__ in_pid,
    const int* __restrict__ out_pid,
    float* __restrict__ out,
    float invB)
{
    __shared__ float s_row[NWARP * NPTS];   // per-warp partial row mins
    __shared__ float s_red[6][NWARP];       // cross-warp sum buffer

    const int b = blockIdx.x;
    const int i = threadIdx.x;
    const int lane = i & 31;
    const int wid  = i >> 5;
    const float INF = __int_as_float(0x7f800000);
    const int base = b * NPTS;

    // ---- own column j == i: load reco, mask, raw norm ----
    const float4 r0 = reco[base + i];
    const int my = (out_pid[base + i] != 0);
    float rn0_raw;
    {
        float c = r0.x * r0.x;
        c = fmaf(r0.y, r0.y, c); c = fmaf(r0.z, r0.z, c); c = fmaf(r0.w, r0.w, c);
        rn0_raw = sqrtf(c);
    }
    const float4 rv = my ? r0 : make_float4(BIGC, BIGC, BIGC, BIGC);
    float cx = rv.x, cy = rv.y, cz = rv.z, cw = rv.w;
    float cr;  // |traveling reco|^2
    {
        float c = cx * cx;
        c = fmaf(cy, cy, c); c = fmaf(cz, cz, c); c = fmaf(cw, cw, c);
        cr = c;
    }

    // ---- load 8 rows per lane and pre-pack row pairs for f32x2 ----
    ull tx2[RPL / 2], ty2[RPL / 2], tz2[RPL / 2], tw2[RPL / 2], tn2[RPL / 2];
    float rm[RPL];
    int   mx_self = 0;
    float t0n_self = 0.0f;
    {
        float tnk[RPL];
        float4 tvk[RPL];
        #pragma unroll
        for (int k = 0; k < RPL; k++) {
            const int row = lane + 32 * k;
            const float4 t0 = target[base + row];
            const int m = (in_pid[base + row] != 0);
            if (k == wid) {  // row == i
                mx_self = m;
                float a = t0.x * t0.x;
                a = fmaf(t0.y, t0.y, a); a = fmaf(t0.z, t0.z, a); a = fmaf(t0.w, t0.w, a);
                t0n_self = sqrtf(a);
            }
            tvk[k] = m ? t0 : make_float4(BIGC, BIGC, BIGC, BIGC);
            float a = tvk[k].x * tvk[k].x;
            a = fmaf(tvk[k].y, tvk[k].y, a);
            a = fmaf(tvk[k].z, tvk[k].z, a);
            a = fmaf(tvk[k].w, tvk[k].w, a);
            tnk[k] = a;
            rm[k] = INF;
        }
        #pragma unroll
        for (int p = 0; p < RPL / 2; p++) {
            PACK2(tx2[p], tvk[2 * p].x, tvk[2 * p + 1].x);
            PACK2(ty2[p], tvk[2 * p].y, tvk[2 * p + 1].y);
            PACK2(tz2[p], tvk[2 * p].z, tvk[2 * p + 1].z);
            PACK2(tw2[p], tvk[2 * p].w, tvk[2 * p + 1].w);
            PACK2(tn2[p], tnk[2 * p], tnk[2 * p + 1]);
        }
    }
    ull neg2_2; PACK2(neg2_2, -2.0f, -2.0f);

    // ---- shuffle ring: 32 steps; next-reco shfls prefetched to hide latency ----
    float cmin = INF;
    const int src = (lane + 1) & 31;
    #pragma unroll 4
    for (int s = 0; s < 32; s++) {
        // prefetch next traveling reco (latency hidden under the packed math)
        const float nx = __shfl_sync(FULLMASK, cx, src);
        const float ny = __shfl_sync(FULLMASK, cy, src);
        const float nz = __shfl_sync(FULLMASK, cz, src);
        const float nw = __shfl_sync(FULLMASK, cw, src);
        const float nr = __shfl_sync(FULLMASK, cr, src);

        ull rx2, ry2, rz2, rw2, rn2;
        PACK2(rx2, cx, cx);
        PACK2(ry2, cy, cy);
        PACK2(rz2, cz, cz);
        PACK2(rw2, cw, cw);
        PACK2(rn2, cr, cr);

        float pm[RPL / 2];
        #pragma unroll
        for (int p = 0; p < RPL / 2; p++) {
            ull dot2;
            MUL2(dot2, tx2[p], rx2);
            FMA2(dot2, ty2[p], ry2, dot2);
            FMA2(dot2, tz2[p], rz2, dot2);
            FMA2(dot2, tw2[p], rw2, dot2);
            ull d2p;
            FMA2(d2p, neg2_2, dot2, tn2[p]);   // tn - 2*dot
            ADD2(d2p, d2p, rn2);               // + rn
            float a, c2;
            UNPK2(a, c2, d2p);
            rm[2 * p]     = fminf(rm[2 * p], a);
            rm[2 * p + 1] = fminf(rm[2 * p + 1], c2);
            pm[p] = fminf(a, c2);
        }
        const float tr = fminf(fminf(pm[0], pm[1]), fminf(pm[2], pm[3]));
        cmin = fminf(cmin, tr);
        cmin = __shfl_sync(FULLMASK, cmin, src);

        cx = nx; cy = ny; cz = nz; cw = nw; cr = nr;
    }
    // cmin is now the full column min for column i.

    // ---- combine per-warp partial row mins via smem slabs ----
    #pragma unroll
    for (int k = 0; k < RPL; k++)
        s_row[wid * NPTS + lane + 32 * k] = rm[k];
    __syncthreads();

    float rowm = s_row[i];
    #pragma unroll
    for (int w = 1; w < NWARP; w++) rowm = fminf(rowm, s_row[w * NPTS + i]);

    // ---- per-thread contributions (sqrt clamped: dot-trick can round <0) ----
    float v[6];
    v[0] = mx_self ? 1.0f : 0.0f;                              // sum fx
    v[1] = my ? 1.0f : 0.0f;                                   // sum fy
    v[2] = mx_self ? sqrtf(fmaxf(rowm, 0.0f)) : 0.0f;          // sum_xy
    v[3] = my ? sqrtf(fmaxf(cmin, 0.0f)) : 0.0f;               // sum_yx
    v[4] = mx_self ? t0n_self : 0.0f;                          // fallback sum ||x||
    v[5] = my ? 0.0f : rn0_raw;                                // sum ||y|| zero-pid

    #pragma unroll
    for (int k = 0; k < 6; k++) {
        const float ws = warp_sum(v[k]);
        if (lane == 0) s_red[k][wid] = ws;
    }
    __syncthreads();

    if (i == 0) {
        float s[6];
        #pragma unroll
        for (int k = 0; k < 6; k++) {
            float acc = 0.0f;
            #pragma unroll
            for (int w = 0; w < NWARP; w++) acc += s_red[k][w];
            s[k] = acc;
        }
        const float sum_fx = s[0], sum_fy = s[1];
        const float sum_xy = s[2], sum_yx = s[3];
        const float sum_fb = s[4], sum_z  = s[5];

        const float n_in  = fmaxf(1.0f, sum_fx);
        const float n_out = fmaxf(1.0f, sum_fy);

        float per_nonzero;
        if (sum_fy == 0.0f) {
            per_nonzero = sum_fb / n_in;              // no valid reco
        } else if (sum_fx == 0.0f) {
            per_nonzero = 0.0f;                        // no valid target
        } else {
            per_nonzero = 0.5f * (sum_xy / n_out + sum_yx / n_in);
        }
        const float per_zero = sum_z / fmaxf(1.0f, (float)NPTS - sum_fy);

        atomicAdd(&out[0], per_nonzero * invB);
        atomicAdd(&out[1], per_zero * invB);
    }
}

extern "C" void kernel_launch(void* const* d_in, const int* in_sizes, int n_in,
                              void* d_out, int out_size)
{
    const float4* target  = (const float4*)d_in[0];
    const float4* reco    = (const float4*)d_in[1];
    const int*    in_pid  = (const int*)d_in[2];
    const int*    out_pid = (const int*)d_in[3];
    float*        out     = (float*)d_out;

    const int B = in_sizes[2] / NPTS;

    cudaMemsetAsync(out, 0, 2 * sizeof(float));
    chamfer_kernel<<<B, NPTS>>>(target, reco, in_pid, out_pid, out, 1.0f / (float)B);
}